// round 14
// baseline (speedup 1.0000x reference)
#include <cuda_runtime.h>
#include <cuda_fp16.h>
#include <cstdint>

#define B_    8
#define CIN   64
#define HDIM  56
#define WDIM  56
#define HW    3136
#define NPX   25088
#define KTOT  576

// qkv: proj 0 (q) and 1 (k) in "t-layout" [px][c*8+head]
//      (q pre-scaled by log2e/sqrt(512)); proj 2 (v) natural [px][head*64+c].
__device__ __half g_qkvh[3ull * NPX * 512];
__device__ __half g_xh[(unsigned long long)NPX * 64];      // [b][h][w][ic] f16 (3.2MB)
__device__ __half g_Wth[3ull * 512 * KTOT];                // [proj][row][k]
__device__ __half g_Wuh[64 * 512];                         // [co][k]

__device__ __forceinline__ void cp_async16(void* smem, const void* gmem) {
    unsigned saddr = (unsigned)__cvta_generic_to_shared(smem);
    asm volatile("cp.async.cg.shared.global [%0], [%1], 16;" :: "r"(saddr), "l"(gmem));
}
__device__ __forceinline__ void cp_async16z(void* smem, const void* gmem, bool ok) {
    unsigned saddr = (unsigned)__cvta_generic_to_shared(smem);
    int ssz = ok ? 16 : 0;
    asm volatile("cp.async.cg.shared.global [%0], [%1], 16, %2;"
                 :: "r"(saddr), "l"(gmem), "r"(ssz));
}
__device__ __forceinline__ void cp_commit() { asm volatile("cp.async.commit_group;"); }
__device__ __forceinline__ void cp_wait0() { asm volatile("cp.async.wait_group 0;"); }
__device__ __forceinline__ void cp_wait1() { asm volatile("cp.async.wait_group 1;"); }

__device__ __forceinline__ void ldsm_x4(uint32_t* r, uint32_t saddr) {
    asm volatile("ldmatrix.sync.aligned.m8n8.x4.shared.b16 {%0,%1,%2,%3}, [%4];"
                 : "=r"(r[0]), "=r"(r[1]), "=r"(r[2]), "=r"(r[3]) : "r"(saddr));
}

#define MMA_F16(acc, a, b)                                                      \
    asm volatile(                                                               \
        "mma.sync.aligned.m16n8k16.row.col.f32.f16.f16.f32 "                    \
        "{%0,%1,%2,%3}, {%4,%5,%6,%7}, {%8,%9}, {%0,%1,%2,%3};"                 \
        : "+f"((acc)[0]), "+f"((acc)[1]), "+f"((acc)[2]), "+f"((acc)[3])        \
        : "r"((a)[0]), "r"((a)[1]), "r"((a)[2]), "r"((a)[3]),                   \
          "r"((b)[0]), "r"((b)[1]))

#define MMA_F16K8(acc, a, b)                                                    \
    asm volatile(                                                               \
        "mma.sync.aligned.m16n8k8.row.col.f32.f16.f16.f32 "                     \
        "{%0,%1,%2,%3}, {%4,%5}, {%6}, {%0,%1,%2,%3};"                          \
        : "+f"((acc)[0]), "+f"((acc)[1]), "+f"((acc)[2]), "+f"((acc)[3])        \
        : "r"((a)[0]), "r"((a)[1]), "r"(b))

__device__ __forceinline__ uint32_t packh2(float lo, float hi) {
    __half2 h = __floats2half2_rn(lo, hi);
    return *(uint32_t*)&h;
}
__device__ __forceinline__ uint32_t ex2h2(uint32_t x) {
    uint32_t r;
    asm("ex2.approx.f16x2 %0, %1;" : "=r"(r) : "r"(x));
    return r;
}

// ---------------------------------------------------------------------------
// Weight prep. q/k rows permuted to t-layout; log2e/sqrt(512) folded into Wq.
// ---------------------------------------------------------------------------
__global__ void prep_wh(const float* __restrict__ Wq, const float* __restrict__ Wk,
                        const float* __restrict__ Wv, const float* __restrict__ Wu) {
    int idx = blockIdx.x * blockDim.x + threadIdx.x;
    const int tot = 3 * 512 * KTOT;
    if (idx < tot) {
        int k = idx % KTOT;
        int r = (idx / KTOT) & 511;
        int proj = idx / (KTOT * 512);
        int tap = k >> 6;
        int ic = k & 63;
        int oc = (proj < 2) ? ((r & 7) * 64 + (r >> 3)) : r;
        const float* src = (proj == 0) ? Wq : ((proj == 1) ? Wk : Wv);
        float w = src[(oc * 64 + ic) * 9 + tap];
        if (proj == 0) w *= 0.06375872303f;   // log2(e)/sqrt(512)
        g_Wth[idx] = __float2half_rn(w);
    }
    if (idx < 64 * 512) {
        g_Wuh[idx] = __float2half_rn(Wu[idx]);
    }
}

// ---------------------------------------------------------------------------
// x transpose to pixel-major f16.
// ---------------------------------------------------------------------------
__global__ __launch_bounds__(256) void xpose(const float* __restrict__ x) {
    __shared__ float xs[64][57];
    const int b = blockIdx.x / HDIM;
    const int h = blockIdx.x % HDIM;
    const int tid = threadIdx.x;

    for (int i = tid; i < 64 * 56; i += 256) {
        int ic = i / 56;
        int w = i - ic * 56;
        xs[ic][w] = x[((size_t)(b * CIN + ic)) * HW + h * WDIM + w];
    }
    __syncthreads();

    __half* outb = g_xh + ((size_t)(b * HW + h * WDIM)) * 64;
    for (int i = tid; i < 56 * 64; i += 256) {
        int w = i >> 6;
        int ic = i & 63;
        outb[(size_t)w * 64 + ic] = __float2half_rn(xs[ic][w]);
    }
}

// ---------------------------------------------------------------------------
// qkv conv GEMM (round-13 proven): implicit im2col from g_xh, f16 mma +
// ldmatrix, BM=128 BN=128 BK=32, 128 threads, warp tile 64x64.
// ---------------------------------------------------------------------------
#define NITER 18
#define ASTR 40

__global__ __launch_bounds__(128) void conv_f16() {
    __shared__ __half As[2][128][ASTR];
    __shared__ __half Bs[2][128][ASTR];

    const int tid = threadIdx.x;
    const int warp = tid >> 5;
    const int lane = tid & 31;
    const int g = lane >> 2;
    const int t = lane & 3;

    const int px0 = blockIdx.x * 128;
    const int oc0 = blockIdx.y * 128;
    const int proj = blockIdx.z;
    const int warpM = (warp & 1) * 64;
    const int warpN = (warp >> 1) * 64;

    const __half* bsrc = g_Wth + ((size_t)proj * 512 + oc0) * KTOT;

    const int lr = lane & 7;
    const int a_row = lr + 8 * ((lane >> 3) & 1);
    const int a_col = 8 * ((lane >> 4) & 1);
    const int b_row = lr + 8 * ((lane >> 4) & 1);
    const int b_col = 8 * ((lane >> 3) & 1);

    const uint32_t sA = (uint32_t)__cvta_generic_to_shared(&As[0][0][0]);
    const uint32_t sB = (uint32_t)__cvta_generic_to_shared(&Bs[0][0][0]);
    const uint32_t bufstep = 128 * ASTR * 2;

    int myrow[4], myc[4], pb[4], ph[4], pw[4];
    #pragma unroll
    for (int i = 0; i < 4; i++) {
        int id = i * 128 + tid;
        myrow[i] = id >> 2;
        myc[i] = id & 3;
        int px = px0 + myrow[i];
        int b = px / HW;
        int rem = px - b * HW;
        ph[i] = rem / WDIM;
        pw[i] = rem - ph[i] * WDIM;
        pb[i] = b;
    }

    float acc[4][8][4];
    #pragma unroll
    for (int mt = 0; mt < 4; mt++)
        #pragma unroll
        for (int nt = 0; nt < 8; nt++)
            #pragma unroll
            for (int r = 0; r < 4; r++) acc[mt][nt][r] = 0.f;

    auto fill = [&](int buf, int kk) {
        const int tap = kk >> 1;
        const int dr = tap / 3 - 1;
        const int dc = tap % 3 - 1;
        const int ic0 = (kk & 1) * 32;
        const int kof = kk * 32;
        #pragma unroll
        for (int i = 0; i < 4; i++) {
            int hh = ph[i] + dr;
            int ww = pw[i] + dc;
            bool ok = ((unsigned)hh < HDIM) && ((unsigned)ww < WDIM);
            int hc = ok ? hh : 0;
            int wc = ok ? ww : 0;
            const __half* srcA =
                g_xh + ((size_t)(pb[i] * HW + hc * WDIM + wc) * 64 + ic0 + myc[i] * 8);
            cp_async16z(&As[buf][myrow[i]][myc[i] * 8], srcA, ok);
            cp_async16(&Bs[buf][myrow[i]][myc[i] * 8],
                       bsrc + (size_t)myrow[i] * KTOT + kof + myc[i] * 8);
        }
        cp_commit();
    };

    fill(0, 0);
    fill(1, 1);

    for (int kk = 0; kk < NITER; kk++) {
        const int buf = kk & 1;
        if (kk == NITER - 1) cp_wait0(); else cp_wait1();
        __syncthreads();

        const uint32_t aBase = sA + buf * bufstep;
        const uint32_t bBase = sB + buf * bufstep;

        #pragma unroll
        for (int ks = 0; ks < 2; ks++) {
            const int kb = ks * 16;
            uint32_t af[4][4];
            #pragma unroll
            for (int mt = 0; mt < 4; mt++)
                ldsm_x4(af[mt], aBase + ((warpM + mt * 16 + a_row) * ASTR + kb + a_col) * 2);
            uint32_t bf[8][2];
            #pragma unroll
            for (int ntp = 0; ntp < 4; ntp++) {
                uint32_t tmp[4];
                ldsm_x4(tmp, bBase + ((warpN + ntp * 16 + b_row) * ASTR + kb + b_col) * 2);
                bf[2 * ntp][0] = tmp[0];
                bf[2 * ntp][1] = tmp[1];
                bf[2 * ntp + 1][0] = tmp[2];
                bf[2 * ntp + 1][1] = tmp[3];
            }
            #pragma unroll
            for (int mt = 0; mt < 4; mt++)
                #pragma unroll
                for (int nt = 0; nt < 8; nt++)
                    MMA_F16(acc[mt][nt], af[mt], bf[nt]);
        }

        if (kk + 2 < NITER) {
            __syncthreads();
            fill(buf, kk + 2);
        }
    }

    __half* outp = g_qkvh + (size_t)proj * NPX * 512;
    #pragma unroll
    for (int mt = 0; mt < 4; mt++) {
        #pragma unroll
        for (int nt = 0; nt < 8; nt++) {
            int r0 = px0 + warpM + mt * 16 + g;
            int c0 = oc0 + warpN + nt * 8 + 2 * t;
            *(__half2*)(outp + (size_t)r0 * 512 + c0) =
                __floats2half2_rn(acc[mt][nt][0], acc[mt][nt][1]);
            *(__half2*)(outp + (size_t)(r0 + 8) * 512 + c0) =
                __floats2half2_rn(acc[mt][nt][2], acc[mt][nt][3]);
        }
    }
}

// ---------------------------------------------------------------------------
// FUSED attention + Wu 1x1 conv + ReLU.
// 512 threads = 16 warps = 16 pixels/block; grid = NPX/16 = 1568.
// Phase 1: per-warp tensor-core attention (round-12 proven), O -> smem Att.
// Phase 2: wu GEMM M=16(px) N=64(co) K=512, split-K across 8 warps
//          (warps 0-3: k<256, warps 4-7: k>=256), fp32 partial reduce via smem.
// ---------------------------------------------------------------------------
#define ASTT 520                // Att row stride in halves (65*16B, conflict-free)
#define WST2 40                 // Wu tile row stride in halves

__global__ __launch_bounds__(512) void attnwu_f16(float* __restrict__ out) {
    __shared__ __half Att[16][ASTT];        // 16.6 KB
    __shared__ __half Ws[2][2][64][WST2];   // [stage][khalf][co][k] 20.5 KB

    const int tid = threadIdx.x;
    const int warp = tid >> 5;
    const int lane = tid & 31;
    const int g = lane >> 2;
    const int t = lane & 3;

    const int px0 = blockIdx.x * 16;

    // ---- prefetch Wu k-chunks for phase 2 (independent of phase 1) ----
    auto fillw = [&](int stage, int it) {
        int kh = tid >> 8;            // 0/1
        int r2 = tid & 255;
        int row = r2 >> 2;            // 0..63
        int c = r2 & 3;               // 0..3
        cp_async16(&Ws[stage][kh][row][c * 8],
                   g_Wuh + (size_t)row * 512 + kh * 256 + it * 32 + c * 8);
        cp_commit();
    };
    fillw(0, 0);
    fillw(1, 1);

    // =============== Phase 1: attention (1 warp = 1 pixel) ===============
    {
        const int p = px0 + warp;
        const size_t base = (size_t)p * 512;
        const __half* qp = g_qkvh + base;
        const __half* kp = g_qkvh + (size_t)NPX * 512 + base;
        const __half* vp = g_qkvh + 2ull * NPX * 512 + base;

        uint32_t kb[8];
        #pragma unroll
        for (int nt = 0; nt < 8; nt++)
            kb[nt] = *(const uint32_t*)&kp[(nt * 8 + g) * 8 + 2 * t];

        uint32_t vb[4][2];
        #pragma unroll
        for (int q = 0; q < 4; q++) {
            vb[q][0] = *(const uint32_t*)&vp[g * 64 + 16 * q + 2 * t];
            vb[q][1] = *(const uint32_t*)&vp[g * 64 + 16 * q + 8 + 2 * t];
        }

        const uint32_t ONESH2 = 0x3C003C00u;
        uint32_t bones[2] = {ONESH2, ONESH2};

        #pragma unroll
        for (int mt = 0; mt < 4; mt++) {
            uint32_t aq[2];
            aq[0] = *(const uint32_t*)&qp[(mt * 16 + g) * 8 + 2 * t];
            aq[1] = *(const uint32_t*)&qp[(mt * 16 + 8 + g) * 8 + 2 * t];

            float S[8][4];
            #pragma unroll
            for (int nt = 0; nt < 8; nt++) {
                S[nt][0] = 0.f; S[nt][1] = 0.f; S[nt][2] = 0.f; S[nt][3] = 0.f;
                MMA_F16K8(S[nt], aq, kb[nt]);
            }

            uint32_t pa[4][4];
            #pragma unroll
            for (int q = 0; q < 4; q++) {
                pa[q][0] = ex2h2(packh2(S[2 * q][0], S[2 * q][1]));
                pa[q][1] = ex2h2(packh2(S[2 * q][2], S[2 * q][3]));
                pa[q][2] = ex2h2(packh2(S[2 * q + 1][0], S[2 * q + 1][1]));
                pa[q][3] = ex2h2(packh2(S[2 * q + 1][2], S[2 * q + 1][3]));
            }

            float osum[4] = {0.f, 0.f, 0.f, 0.f};
            float o[4] = {0.f, 0.f, 0.f, 0.f};
            #pragma unroll
            for (int q = 0; q < 4; q++) {
                MMA_F16(osum, pa[q], bones);
                MMA_F16(o, pa[q], vb[q]);
            }
            const float inv0 = 1.0f / osum[0];
            const float inv1 = 1.0f / osum[2];

            __half* ap = &Att[warp][(mt * 16 + g) * 8 + 2 * t];
            *(__half2*)ap = __floats2half2_rn(o[0] * inv0, o[1] * inv0);
            *(__half2*)(ap + 64) = __floats2half2_rn(o[2] * inv1, o[3] * inv1);
        }
    }
    __syncthreads();   // Att complete

    // =============== Phase 2: wu GEMM M=16 N=64 K=512 (split-K) ===========
    const int khalf = (warp >> 2) & 1;     // warps 0-3: 0, 4-7: 1
    const int n0 = (warp & 3) * 16;
    const bool active = (warp < 8);

    const int lr = lane & 7;
    const int a_row = lr + 8 * ((lane >> 3) & 1);
    const int a_col = 8 * ((lane >> 4) & 1);
    const int b_row = lr + 8 * ((lane >> 4) & 1);
    const int b_col = 8 * ((lane >> 3) & 1);

    const uint32_t sAtt = (uint32_t)__cvta_generic_to_shared(&Att[0][0]);
    const uint32_t sWs = (uint32_t)__cvta_generic_to_shared(&Ws[0][0][0][0]);
    const uint32_t wstage = 2 * 64 * WST2 * 2;   // bytes per stage
    const uint32_t whalf = 64 * WST2 * 2;        // bytes per khalf

    float acc[2][4];
    #pragma unroll
    for (int nt = 0; nt < 2; nt++)
        #pragma unroll
        for (int r = 0; r < 4; r++) acc[nt][r] = 0.f;

    for (int it = 0; it < 8; it++) {
        const int buf = it & 1;
        if (it == 7) cp_wait0(); else cp_wait1();
        __syncthreads();

        if (active) {
            const uint32_t wBase = sWs + buf * wstage + khalf * whalf;
            #pragma unroll
            for (int ks = 0; ks < 2; ks++) {
                const int kcol = khalf * 256 + it * 32 + ks * 16;
                uint32_t af[4];
                ldsm_x4(af, sAtt + (a_row * ASTT + kcol + a_col) * 2);
                uint32_t bf[2][2];
                {
                    uint32_t tmp[4];
                    ldsm_x4(tmp, wBase + ((n0 + b_row) * WST2 + ks * 16 + b_col) * 2);
                    bf[0][0] = tmp[0];
                    bf[0][1] = tmp[1];
                    bf[1][0] = tmp[2];
                    bf[1][1] = tmp[3];
                }
                MMA_F16(acc[0], af, bf[0]);
                MMA_F16(acc[1], af, bf[1]);
            }
        }

        if (it + 2 < 8) {
            __syncthreads();
            fillw(buf, it + 2);
        }
    }
    __syncthreads();   // all Att reads + Ws use done

    // reduce the two k-halves via smem (reuse Att storage as fp32)
    float* red = (float*)&Att[0][0];   // 4 ntile * 2 n8 * 16 row * 8 col = 4KB
    if (active && khalf == 1) {
        #pragma unroll
        for (int nt = 0; nt < 2; nt++) {
            int basei = ((warp & 3) * 2 + nt) * 128;
            red[basei + g * 8 + 2 * t] = acc[nt][0];
            red[basei + g * 8 + 2 * t + 1] = acc[nt][1];
            red[basei + (g + 8) * 8 + 2 * t] = acc[nt][2];
            red[basei + (g + 8) * 8 + 2 * t + 1] = acc[nt][3];
        }
    }
    __syncthreads();

    if (active && khalf == 0) {
        const int b = px0 / HW;
        const int hwb = px0 - b * HW;
        #pragma unroll
        for (int nt = 0; nt < 2; nt++) {
            int basei = ((warp & 3) * 2 + nt) * 128;
            float v0 = acc[nt][0] + red[basei + g * 8 + 2 * t];
            float v1 = acc[nt][1] + red[basei + g * 8 + 2 * t + 1];
            float v2 = acc[nt][2] + red[basei + (g + 8) * 8 + 2 * t];
            float v3 = acc[nt][3] + red[basei + (g + 8) * 8 + 2 * t + 1];
            int c0 = n0 + nt * 8 + 2 * t;
            float* o0 = out + ((size_t)(b * 64 + c0)) * HW + hwb;
            float* o1 = out + ((size_t)(b * 64 + c0 + 1)) * HW + hwb;
            o0[g] = fmaxf(v0, 0.f);
            o1[g] = fmaxf(v1, 0.f);
            o0[g + 8] = fmaxf(v2, 0.f);
            o1[g + 8] = fmaxf(v3, 0.f);
        }
    }
}

// ---------------------------------------------------------------------------
extern "C" void kernel_launch(void* const* d_in, const int* in_sizes, int n_in,
                              void* d_out, int out_size) {
    const float* x  = (const float*)d_in[0];
    const float* Wq = (const float*)d_in[1];
    const float* Wk = (const float*)d_in[2];
    const float* Wv = (const float*)d_in[3];
    const float* Wu = (const float*)d_in[4];
    float* out = (float*)d_out;

    prep_wh<<<(3 * 512 * KTOT + 255) / 256, 256>>>(Wq, Wk, Wv, Wu);
    xpose<<<B_ * HDIM, 256>>>(x);
    conv_f16<<<dim3(NPX / 128, 4, 3), 128>>>();
    attnwu_f16<<<NPX / 16, 512>>>(out);
}